// round 1
// baseline (speedup 1.0000x reference)
#include <cuda_runtime.h>
#include <math.h>
#include <stdint.h>

// ============================================================================
// Masked ViT context encoder (I-JEPA style), fp32 baseline.
// B=64, T=196 patches, D=768, 12 heads x 64, 12 layers, FFN 3072.
// Sc (max visible tokens) is derived from out_size at launch time.
// ============================================================================

#define BATCH    64
#define N_TOK    196
#define D_MODEL  768
#define N_HEADS  12
#define HEAD_DIM 64
#define N_LAYERS 12
#define FF_DIM   3072
#define M_MAX    (BATCH * N_TOK)

// ---------------- scratch (device globals; no allocation allowed) -----------
__device__ int   g_order[BATCH * N_TOK];
__device__ int   g_len[BATCH];
__device__ float g_im2col[(size_t)M_MAX * D_MODEL];
__device__ float g_X[(size_t)M_MAX * D_MODEL];
__device__ float g_qkv[(size_t)M_MAX * 3 * D_MODEL];
__device__ float g_attn[(size_t)M_MAX * D_MODEL];
__device__ float g_proj[(size_t)M_MAX * D_MODEL];
__device__ float g_ffn[(size_t)M_MAX * FF_DIM];
__device__ float g_scores[(size_t)BATCH * N_HEADS * N_TOK * N_TOK];

// ---------------------------------------------------------------------------
// Mask parse. The reference mask is jax bool; the harness may hand it to us as
// int32, uint8, or float32. Detect from byte patterns in the first 12544 bytes
// (valid under all three interpretations), then build per-batch visible-index
// lists (ascending == stable argsort of ~mask) and lengths.
// ---------------------------------------------------------------------------
__global__ void mask_kernel(const unsigned char* __restrict__ mp)
{
    __shared__ int s_type;
    int tid = threadIdx.x;
    if (tid == 0) {
        bool big = false, misal = false;
        for (int i = 0; i < BATCH * N_TOK; i++) {
            unsigned char v = mp[i];
            if (v >= 2) big = true;          // float32 bit patterns (0x80 / 0x3F)
            else if (v && (i & 3)) misal = true; // uint8 bools hit non-word offsets
        }
        s_type = big ? 2 : (misal ? 1 : 0);  // 2=float32, 1=uint8, 0=int32
    }
    __syncthreads();
    int type = s_type;
    int b = tid;
    if (b < BATCH) {
        int cnt = 0;
        for (int t = 0; t < N_TOK; t++) {
            int idx = b * N_TOK + t;
            bool m;
            if (type == 2)      m = (((const float*)mp)[idx] != 0.0f);
            else if (type == 1) m = (mp[idx] != 0);
            else                m = (((const int*)mp)[idx] != 0);
            if (m) { g_order[b * N_TOK + cnt] = t; cnt++; }
        }
        g_len[b] = cnt;
    }
}

// ---------------------------------------------------------------------------
// im2col gather for visible tokens: A[m, k] with k = c*256 + py*16 + px.
// Pad rows are zeroed (they stay zero through the patch GEMM epilogue).
// ---------------------------------------------------------------------------
__global__ void im2col_kernel(const float* __restrict__ x, int Sc)
{
    int s = blockIdx.x, b = blockIdx.y;
    int m = b * Sc + s;
    float* dst = g_im2col + (size_t)m * D_MODEL;
    if (s >= g_len[b]) {
        for (int k = threadIdx.x; k < D_MODEL; k += blockDim.x) dst[k] = 0.0f;
        return;
    }
    int t = g_order[b * N_TOK + s];
    int gy = t / 14, gx = t % 14;
    const float* xb = x + (size_t)b * 3 * 224 * 224;
    for (int k = threadIdx.x; k < D_MODEL; k += blockDim.x) {
        int c = k >> 8, r = (k >> 4) & 15, cc = k & 15;
        dst[k] = xb[((size_t)c * 224 + (gy * 16 + r)) * 224 + (gx * 16 + cc)];
    }
}

// ---------------------------------------------------------------------------
// Generic fp32 GEMM: C[M,N] = A[M,K](row-major, lda) * B[N,K](row-major)^T
// FLAGS: bit0 = add bias[n], bit1 = exact GELU.
// Tiles 128x128x16, 256 threads, 8x8 per thread. N must be a multiple of 128
// (768/2304/3072 all are). M is bounds-checked.
// ---------------------------------------------------------------------------
template<int FLAGS>
__global__ void __launch_bounds__(256, 2) sgemm_kernel(
    const float* __restrict__ A, int lda,
    const float* __restrict__ Bw,
    const float* __restrict__ bias,
    float* __restrict__ C, int ldc,
    int M, int N, int K)
{
    __shared__ float As[16][128];
    __shared__ float Bs[16][128];
    const int tid  = threadIdx.x;
    const int brow = blockIdx.y * 128;
    const int bcol = blockIdx.x * 128;
    const int lr = tid >> 2;          // 0..63
    const int lk = (tid & 3) * 4;     // 0,4,8,12
    const int tx = tid & 15, ty = tid >> 4;

    float acc[8][8];
    #pragma unroll
    for (int i = 0; i < 8; i++)
        #pragma unroll
        for (int j = 0; j < 8; j++) acc[i][j] = 0.0f;

    for (int k0 = 0; k0 < K; k0 += 16) {
        #pragma unroll
        for (int half = 0; half < 2; half++) {
            int r  = lr + half * 64;
            int gr = brow + r;
            float4 va = (gr < M) ? *(const float4*)(A + (size_t)gr * lda + k0 + lk)
                                 : make_float4(0.f, 0.f, 0.f, 0.f);
            As[lk + 0][r] = va.x; As[lk + 1][r] = va.y;
            As[lk + 2][r] = va.z; As[lk + 3][r] = va.w;
            int gn = bcol + r;
            float4 vb = *(const float4*)(Bw + (size_t)gn * K + k0 + lk);
            Bs[lk + 0][r] = vb.x; Bs[lk + 1][r] = vb.y;
            Bs[lk + 2][r] = vb.z; Bs[lk + 3][r] = vb.w;
        }
        __syncthreads();
        #pragma unroll
        for (int kk = 0; kk < 16; kk++) {
            float a[8], bb[8];
            const float4* ap = (const float4*)&As[kk][ty * 8];
            const float4* bp = (const float4*)&Bs[kk][tx * 8];
            float4 a0 = ap[0], a1 = ap[1], b0 = bp[0], b1 = bp[1];
            a[0]=a0.x; a[1]=a0.y; a[2]=a0.z; a[3]=a0.w;
            a[4]=a1.x; a[5]=a1.y; a[6]=a1.z; a[7]=a1.w;
            bb[0]=b0.x; bb[1]=b0.y; bb[2]=b0.z; bb[3]=b0.w;
            bb[4]=b1.x; bb[5]=b1.y; bb[6]=b1.z; bb[7]=b1.w;
            #pragma unroll
            for (int i = 0; i < 8; i++)
                #pragma unroll
                for (int j = 0; j < 8; j++) acc[i][j] += a[i] * bb[j];
        }
        __syncthreads();
    }

    #pragma unroll
    for (int i = 0; i < 8; i++) {
        int gr = brow + ty * 8 + i;
        if (gr < M) {
            float* crow = C + (size_t)gr * ldc + bcol + tx * 8;
            #pragma unroll
            for (int j = 0; j < 8; j++) {
                float v = acc[i][j];
                if (FLAGS & 1) v += bias[bcol + tx * 8 + j];
                if (FLAGS & 2) v = 0.5f * v * (1.0f + erff(v * 0.70710678118654752440f));
                crow[j] = v;
            }
        }
    }
}

// ---------------------------------------------------------------------------
// Patch epilogue: ctx += patch_b + pos_embed[token]; zero pad rows.
// ---------------------------------------------------------------------------
__global__ void patch_epi_kernel(const float* __restrict__ pb,
                                 const float* __restrict__ pos, int Sc)
{
    int s = blockIdx.x, b = blockIdx.y;
    int m = b * Sc + s;
    float* row = g_X + (size_t)m * D_MODEL;
    if (s >= g_len[b]) {
        for (int d = threadIdx.x; d < D_MODEL; d += blockDim.x) row[d] = 0.0f;
        return;
    }
    int t = g_order[b * N_TOK + s];
    const float* pr = pos + (size_t)t * D_MODEL;
    for (int d = threadIdx.x; d < D_MODEL; d += blockDim.x)
        row[d] = row[d] + pb[d] + pr[d];
}

// ---------------------------------------------------------------------------
// Attention: scores, softmax, P*V (3 small kernels).
// ---------------------------------------------------------------------------
__global__ void scores_kernel(int Sc)
{
    int bh = blockIdx.z;
    int b = bh / N_HEADS, h = bh % N_HEADS;
    int q0 = blockIdx.y * 16, k0 = blockIdx.x * 16;
    __shared__ float qs[16][65], ks[16][65];
    int tx = threadIdx.x, ty = threadIdx.y;

    {
        int q = q0 + ty;
        if (q < Sc) {
            const float* qp = g_qkv + ((size_t)(b * Sc + q)) * (3 * D_MODEL) + h * HEAD_DIM;
            for (int j = tx; j < HEAD_DIM; j += 16) qs[ty][j] = qp[j];
        } else {
            for (int j = tx; j < HEAD_DIM; j += 16) qs[ty][j] = 0.0f;
        }
        int k = k0 + ty;
        if (k < Sc) {
            const float* kp = g_qkv + ((size_t)(b * Sc + k)) * (3 * D_MODEL) + D_MODEL + h * HEAD_DIM;
            for (int j = tx; j < HEAD_DIM; j += 16) ks[ty][j] = kp[j];
        } else {
            for (int j = tx; j < HEAD_DIM; j += 16) ks[ty][j] = 0.0f;
        }
    }
    __syncthreads();

    int q = q0 + ty, k = k0 + tx;
    if (q < Sc && k < Sc) {
        float acc = 0.0f;
        #pragma unroll
        for (int j = 0; j < HEAD_DIM; j++) acc += qs[ty][j] * ks[tx][j];
        acc *= 0.125f;                       // 1/sqrt(64)
        if (k >= g_len[b]) acc = -1e30f;     // mask padded keys
        g_scores[((size_t)bh * Sc + q) * Sc + k] = acc;
    }
}

__global__ void softmax_kernel(int Sc)
{
    int q = blockIdx.x, bh = blockIdx.y;
    float* row = g_scores + ((size_t)bh * Sc + q) * Sc;
    int tid = threadIdx.x;  // 128 threads
    __shared__ float sh[4], sh2[4];

    float mx = -3.4e38f;
    for (int i = tid; i < Sc; i += 128) mx = fmaxf(mx, row[i]);
    #pragma unroll
    for (int o = 16; o; o >>= 1) mx = fmaxf(mx, __shfl_down_sync(0xffffffffu, mx, o));
    if ((tid & 31) == 0) sh[tid >> 5] = mx;
    __syncthreads();
    mx = fmaxf(fmaxf(sh[0], sh[1]), fmaxf(sh[2], sh[3]));

    float sum = 0.0f;
    for (int i = tid; i < Sc; i += 128) {
        float e = __expf(row[i] - mx);
        row[i] = e;
        sum += e;
    }
    #pragma unroll
    for (int o = 16; o; o >>= 1) sum += __shfl_down_sync(0xffffffffu, sum, o);
    if ((tid & 31) == 0) sh2[tid >> 5] = sum;
    __syncthreads();
    sum = sh2[0] + sh2[1] + sh2[2] + sh2[3];
    float inv = 1.0f / sum;
    for (int i = tid; i < Sc; i += 128) row[i] *= inv;
}

__global__ void pv_kernel(int Sc)
{
    // grid (4, ceil(Sc/16), B*H), block (16,16)
    int bh = blockIdx.z;
    int b = bh / N_HEADS, h = bh % N_HEADS;
    int q0 = blockIdx.y * 16, j0 = blockIdx.x * 16;
    __shared__ float ps[16][17], vs[16][17];
    int tx = threadIdx.x, ty = threadIdx.y;
    float acc = 0.0f;

    for (int kk0 = 0; kk0 < Sc; kk0 += 16) {
        int q = q0 + ty, k = kk0 + tx;
        ps[ty][tx] = (q < Sc && k < Sc) ? g_scores[((size_t)bh * Sc + q) * Sc + k] : 0.0f;
        int kv = kk0 + ty;
        vs[ty][tx] = (kv < Sc)
            ? g_qkv[((size_t)(b * Sc + kv)) * (3 * D_MODEL) + 2 * D_MODEL + h * HEAD_DIM + j0 + tx]
            : 0.0f;
        __syncthreads();
        #pragma unroll
        for (int kk = 0; kk < 16; kk++) acc += ps[ty][kk] * vs[kk][tx];
        __syncthreads();
    }
    int q = q0 + ty;
    if (q < Sc)
        g_attn[((size_t)(b * Sc + q)) * D_MODEL + h * HEAD_DIM + j0 + tx] = acc;
}

// ---------------------------------------------------------------------------
// LayerNorm over D=768, optionally adding a residual input first.
// One block (256 threads) per row; 3 elements per thread.
// ---------------------------------------------------------------------------
__device__ __forceinline__ float blockReduce256(float v)
{
    __shared__ float sh[8];
    __syncthreads();   // protect reuse across consecutive calls
    #pragma unroll
    for (int o = 16; o; o >>= 1) v += __shfl_down_sync(0xffffffffu, v, o);
    if ((threadIdx.x & 31) == 0) sh[threadIdx.x >> 5] = v;
    __syncthreads();
    return sh[0] + sh[1] + sh[2] + sh[3] + sh[4] + sh[5] + sh[6] + sh[7];
}

template<bool RESID>
__global__ void ln_kernel(const float* __restrict__ X, const float* __restrict__ Rsd,
                          const float* __restrict__ gma, const float* __restrict__ bta,
                          float* __restrict__ out)
{
    int m = blockIdx.x;
    int tid = threadIdx.x;
    const float* xr = X + (size_t)m * D_MODEL;
    float v[3];
    #pragma unroll
    for (int i = 0; i < 3; i++) {
        int d = tid + 256 * i;
        v[i] = xr[d];
        if (RESID) v[i] += Rsd[(size_t)m * D_MODEL + d];
    }
    float s = blockReduce256(v[0] + v[1] + v[2]);
    float mean = s * (1.0f / 768.0f);
    float q = 0.0f;
    #pragma unroll
    for (int i = 0; i < 3; i++) { float d = v[i] - mean; q += d * d; }
    q = blockReduce256(q);
    float inv = 1.0f / sqrtf(q * (1.0f / 768.0f) + 1e-5f);
    float* orow = out + (size_t)m * D_MODEL;
    #pragma unroll
    for (int i = 0; i < 3; i++) {
        int d = tid + 256 * i;
        orow[d] = (v[i] - mean) * inv * gma[d] + bta[d];
    }
}

// ctx_pad output (True=pad -> 1.0f), appended after ctx when output is a tuple.
__global__ void pad_out_kernel(float* __restrict__ out2, int Sc)
{
    int i = blockIdx.x * blockDim.x + threadIdx.x;
    if (i < BATCH * Sc) {
        int b = i / Sc, s = i % Sc;
        out2[i] = (s >= g_len[b]) ? 1.0f : 0.0f;
    }
}

// ===========================================================================
extern "C" void kernel_launch(void* const* d_in, const int* in_sizes, int n_in,
                              void* d_out, int out_size)
{
    const float* x       = (const float*)d_in[0];
    const void*  mask    = d_in[1];
    const float* patch_w = (const float*)d_in[2];
    const float* patch_b = (const float*)d_in[3];
    const float* pos     = (const float*)d_in[4];
    const float* inw     = (const float*)d_in[5];
    const float* inb     = (const float*)d_in[6];
    const float* outw    = (const float*)d_in[7];
    const float* outb    = (const float*)d_in[8];
    const float* ln1g    = (const float*)d_in[9];
    const float* ln1b    = (const float*)d_in[10];
    const float* f1w     = (const float*)d_in[11];
    const float* f1b     = (const float*)d_in[12];
    const float* f2w     = (const float*)d_in[13];
    const float* f2b     = (const float*)d_in[14];
    const float* ln2g    = (const float*)d_in[15];
    const float* ln2b    = (const float*)d_in[16];
    const float* ng      = (const float*)d_in[17];
    const float* nb      = (const float*)d_in[18];

    // Derive Sc (and tuple-ness) from out_size:
    //   tuple (ctx, ctx_pad): out_size = 64*Sc*768 + 64*Sc = 64*769*Sc
    //   ctx only:             out_size = 64*768*Sc
    // (769 and 768 are coprime and Sc<=196, so the two cases never collide.)
    int Sc; bool tup;
    if (out_size % (64 * 769) == 0 &&
        out_size / (64 * 769) >= 1 && out_size / (64 * 769) <= N_TOK) {
        Sc = out_size / (64 * 769); tup = true;
    } else {
        Sc = out_size / (64 * 768); tup = false;
    }
    if (Sc < 1) Sc = 1;
    if (Sc > N_TOK) Sc = N_TOK;
    const int M  = BATCH * Sc;
    const int MB = (M + 127) / 128;
    const int ST = (Sc + 15) / 16;

    float *pIm, *pX, *pQ, *pA, *pP, *pF;
    cudaGetSymbolAddress((void**)&pIm, g_im2col);
    cudaGetSymbolAddress((void**)&pX,  g_X);
    cudaGetSymbolAddress((void**)&pQ,  g_qkv);
    cudaGetSymbolAddress((void**)&pA,  g_attn);
    cudaGetSymbolAddress((void**)&pP,  g_proj);
    cudaGetSymbolAddress((void**)&pF,  g_ffn);

    // --- mask parse + gather + patch embedding --------------------------------
    mask_kernel<<<1, 64>>>((const unsigned char*)mask);
    im2col_kernel<<<dim3(Sc, BATCH), 256>>>(x, Sc);
    sgemm_kernel<0><<<dim3(6, MB), 256>>>(pIm, D_MODEL, patch_w, nullptr,
                                          pX, D_MODEL, M, D_MODEL, D_MODEL);
    patch_epi_kernel<<<dim3(Sc, BATCH), 256>>>(patch_b, pos, Sc);

    // --- transformer layers ---------------------------------------------------
    for (int l = 0; l < N_LAYERS; l++) {
        const float* Wqkv = inw  + (size_t)l * 3 * D_MODEL * D_MODEL;
        const float* bqkv = inb  + (size_t)l * 3 * D_MODEL;
        const float* Wo   = outw + (size_t)l * D_MODEL * D_MODEL;
        const float* bo   = outb + (size_t)l * D_MODEL;
        const float* W1   = f1w  + (size_t)l * FF_DIM * D_MODEL;
        const float* b1   = f1b  + (size_t)l * FF_DIM;
        const float* W2   = f2w  + (size_t)l * D_MODEL * FF_DIM;
        const float* b2   = f2b  + (size_t)l * D_MODEL;

        // QKV projection
        sgemm_kernel<1><<<dim3(18, MB), 256>>>(pX, D_MODEL, Wqkv, bqkv,
                                               pQ, 3 * D_MODEL, M, 3 * D_MODEL, D_MODEL);
        // attention
        scores_kernel <<<dim3(ST, ST, BATCH * N_HEADS), dim3(16, 16)>>>(Sc);
        softmax_kernel<<<dim3(Sc, BATCH * N_HEADS), 128>>>(Sc);
        pv_kernel     <<<dim3(4, ST, BATCH * N_HEADS), dim3(16, 16)>>>(Sc);
        // output projection
        sgemm_kernel<1><<<dim3(6, MB), 256>>>(pA, D_MODEL, Wo, bo,
                                              pP, D_MODEL, M, D_MODEL, D_MODEL);
        // residual + LN1 (in place on X)
        ln_kernel<true><<<M, 256>>>(pX, pP, ln1g + l * D_MODEL, ln1b + l * D_MODEL, pX);
        // FFN
        sgemm_kernel<3><<<dim3(24, MB), 256>>>(pX, D_MODEL, W1, b1,
                                               pF, FF_DIM, M, FF_DIM, D_MODEL);
        sgemm_kernel<1><<<dim3(6, MB), 256>>>(pF, FF_DIM, W2, b2,
                                              pP, D_MODEL, M, D_MODEL, FF_DIM);
        // residual + LN2 (in place on X)
        ln_kernel<true><<<M, 256>>>(pX, pP, ln2g + l * D_MODEL, ln2b + l * D_MODEL, pX);
    }

    // --- final LN straight into d_out ----------------------------------------
    ln_kernel<false><<<M, 256>>>(pX, nullptr, ng, nb, (float*)d_out);
    if (tup) {
        pad_out_kernel<<<(BATCH * Sc + 255) / 256, 256>>>(
            (float*)d_out + (size_t)M * D_MODEL, Sc);
    }
}

// round 3
// speedup vs baseline: 3.3182x; 3.3182x over previous
#include <cuda_runtime.h>
#include <cuda_bf16.h>
#include <math.h>
#include <stdint.h>

// ============================================================================
// Masked ViT context encoder. R3: GEMMs on warp-level mma.sync (HMMA bf16,
// 3-term hi/lo split, fp32 accum). tcgen05 unavailable (PTX target compute_103
// lacks the 'a' feature set). Attention/LN remain fp32 SIMT this round.
// ============================================================================

#define BATCH    64
#define N_TOK    196
#define D_MODEL  768
#define N_HEADS  12
#define HEAD_DIM 64
#define N_LAYERS 12
#define FF_DIM   3072
#define M_MAX    (BATCH * N_TOK)

// ---------------- scratch (device globals; no allocation allowed) -----------
__device__ int   g_order[BATCH * N_TOK];
__device__ int   g_len[BATCH];
__device__ float g_im2col[(size_t)M_MAX * D_MODEL];
__device__ float g_X[(size_t)M_MAX * D_MODEL];
__device__ float g_qkv[(size_t)M_MAX * 3 * D_MODEL];
__device__ float g_attn[(size_t)M_MAX * D_MODEL];
__device__ float g_proj[(size_t)M_MAX * D_MODEL];
__device__ float g_ffn[(size_t)M_MAX * FF_DIM];
__device__ float g_scores[(size_t)BATCH * N_HEADS * N_TOK * N_TOK];

// bf16 hi/lo split buffers: activations (max K = 3072) and all weights.
__device__ __nv_bfloat16 g_ah[(size_t)M_MAX * FF_DIM];
__device__ __nv_bfloat16 g_al[(size_t)M_MAX * FF_DIM];
__device__ __nv_bfloat16 g_wqkv_h[(size_t)N_LAYERS * 3 * D_MODEL * D_MODEL];
__device__ __nv_bfloat16 g_wqkv_l[(size_t)N_LAYERS * 3 * D_MODEL * D_MODEL];
__device__ __nv_bfloat16 g_wo_h[(size_t)N_LAYERS * D_MODEL * D_MODEL];
__device__ __nv_bfloat16 g_wo_l[(size_t)N_LAYERS * D_MODEL * D_MODEL];
__device__ __nv_bfloat16 g_wf1_h[(size_t)N_LAYERS * FF_DIM * D_MODEL];
__device__ __nv_bfloat16 g_wf1_l[(size_t)N_LAYERS * FF_DIM * D_MODEL];
__device__ __nv_bfloat16 g_wf2_h[(size_t)N_LAYERS * FF_DIM * D_MODEL];
__device__ __nv_bfloat16 g_wf2_l[(size_t)N_LAYERS * FF_DIM * D_MODEL];
__device__ __nv_bfloat16 g_wp_h[(size_t)D_MODEL * D_MODEL];
__device__ __nv_bfloat16 g_wp_l[(size_t)D_MODEL * D_MODEL];

// ============================================================================
// split: fp32 -> (hi bf16, lo bf16), lo = bf16(x - float(hi)). Vectorized x4.
// ============================================================================
__global__ void split_kernel(const float4* __restrict__ src,
                             uint2* __restrict__ hi, uint2* __restrict__ lo, int n4)
{
    int i = blockIdx.x * blockDim.x + threadIdx.x;
    if (i >= n4) return;
    float4 v = src[i];
    __nv_bfloat16 h0 = __float2bfloat16(v.x), h1 = __float2bfloat16(v.y),
                  h2 = __float2bfloat16(v.z), h3 = __float2bfloat16(v.w);
    __nv_bfloat16 l0 = __float2bfloat16(v.x - __bfloat162float(h0));
    __nv_bfloat16 l1 = __float2bfloat16(v.y - __bfloat162float(h1));
    __nv_bfloat16 l2 = __float2bfloat16(v.z - __bfloat162float(h2));
    __nv_bfloat16 l3 = __float2bfloat16(v.w - __bfloat162float(h3));
    uint2 ph, pl;
    ph.x = (uint32_t)__bfloat16_as_ushort(h0) | ((uint32_t)__bfloat16_as_ushort(h1) << 16);
    ph.y = (uint32_t)__bfloat16_as_ushort(h2) | ((uint32_t)__bfloat16_as_ushort(h3) << 16);
    pl.x = (uint32_t)__bfloat16_as_ushort(l0) | ((uint32_t)__bfloat16_as_ushort(l1) << 16);
    pl.y = (uint32_t)__bfloat16_as_ushort(l2) | ((uint32_t)__bfloat16_as_ushort(l3) << 16);
    hi[i] = ph; lo[i] = pl;
}

// ============================================================================
// HMMA GEMM: C[M,N] = (Ah+Al)[M,K] * ((Bh+Bl)[N,K])^T  (AlBl dropped)
// 128x128 CTA tile, K-chunk 64, cp.async double buffer, 8 warps (4m x 2n),
// warp tile 32x64 via m16n8k16 (2 m-tiles x 8 n-tiles).
// flags: bit0 = add bias, bit1 = exact GELU.
// ============================================================================
#define ROW_BYTES   144                 // 64 bf16 (128B) + 16B pad: conflict-free
#define TILE_BYTES  (128 * ROW_BYTES)   // 18432
#define STAGE_BYTES (4 * TILE_BYTES)    // Ah,Al,Bh,Bl = 73728
#define GEMM_SMEM   (2 * STAGE_BYTES)   // 147456

#define CP_ASYNC_16(dst, src) \
    asm volatile("cp.async.cg.shared.global [%0], [%1], 16;" :: "r"(dst), "l"(src))
#define CP_COMMIT() asm volatile("cp.async.commit_group;" ::: "memory")
#define CP_WAIT(n)  asm volatile("cp.async.wait_group %0;" :: "n"(n) : "memory")

#define MMA16816(c, a, b) \
    asm volatile("mma.sync.aligned.m16n8k16.row.col.f32.bf16.bf16.f32 " \
        "{%0,%1,%2,%3}, {%4,%5,%6,%7}, {%8,%9}, {%0,%1,%2,%3};" \
        : "+f"((c)[0]), "+f"((c)[1]), "+f"((c)[2]), "+f"((c)[3]) \
        : "r"((a)[0]), "r"((a)[1]), "r"((a)[2]), "r"((a)[3]), \
          "r"((b)[0]), "r"((b)[1]))

__device__ __forceinline__ uint32_t smem_u32(const void* p) {
    uint32_t a;
    asm("{ .reg .u64 t; cvta.to.shared.u64 t, %1; cvt.u32.u64 %0, t; }"
        : "=r"(a) : "l"(p));
    return a;
}

__global__ void __launch_bounds__(256, 1)
mma_gemm_kernel(const __nv_bfloat16* __restrict__ Ah, const __nv_bfloat16* __restrict__ Al,
                const __nv_bfloat16* __restrict__ Bh, const __nv_bfloat16* __restrict__ Bl,
                const float* __restrict__ bias, float* __restrict__ C,
                int ldc, int M, int K, int flags)
{
    extern __shared__ char smem[];
    const uint32_t smem_base = smem_u32(smem);
    const int tid  = threadIdx.x;
    const int wid  = tid >> 5, lane = tid & 31;
    const int wm   = wid & 3, wn = wid >> 2;     // warp grid 4(m) x 2(n)
    const int brow = blockIdx.y * 128;
    const int bcol = blockIdx.x * 128;
    const int lr   = lane >> 2;                  // 0..7
    const int lc   = (lane & 3) * 2;             // 0,2,4,6

    float acc[2][8][4];
    #pragma unroll
    for (int mt = 0; mt < 2; mt++)
        #pragma unroll
        for (int nt = 0; nt < 8; nt++)
            #pragma unroll
            for (int i = 0; i < 4; i++) acc[mt][nt][i] = 0.0f;

    const int nC = K >> 6;

    // ---- async chunk loader: 4096 x 16B per chunk, 16 per thread -----------
    auto load_chunk = [&](int c, int buf) {
        const int k0 = c << 6;
        const uint32_t tb = smem_base + (uint32_t)buf * STAGE_BYTES;
        #pragma unroll
        for (int j = 0; j < 16; j++) {
            int idx = tid + (j << 8);
            int op  = idx >> 10;          // 0=Ah 1=Al 2=Bh 3=Bl
            int rem = idx & 1023;
            int r   = rem >> 3;           // row 0..127
            int q   = rem & 7;            // 16B chunk
            const __nv_bfloat16* gp;
            if (op < 2) {
                int gr = brow + r;
                if (gr >= M) gr = M - 1;  // clamp; garbage rows discarded in epilogue
                gp = (op ? Al : Ah) + (size_t)gr * K + k0 + (q << 3);
            } else {
                int gn = bcol + r;
                gp = (op == 3 ? Bl : Bh) + (size_t)gn * K + k0 + (q << 3);
            }
            uint32_t dst = tb + (uint32_t)op * TILE_BYTES + (uint32_t)r * ROW_BYTES + (q << 4);
            CP_ASYNC_16(dst, gp);
        }
        CP_COMMIT();
    };

    load_chunk(0, 0);

    for (int c = 0; c < nC; c++) {
        const int buf = c & 1;
        if (c + 1 < nC) { load_chunk(c + 1, buf ^ 1); CP_WAIT(1); }
        else            { CP_WAIT(0); }
        __syncthreads();

        const char* At  = smem + (size_t)buf * STAGE_BYTES;
        const char* Alt = At + TILE_BYTES;
        const char* Bt  = At + 2 * TILE_BYTES;
        const char* Blt = At + 3 * TILE_BYTES;

        #pragma unroll
        for (int ks = 0; ks < 64; ks += 16) {
            uint32_t ah[2][4], al[2][4], bh[8][2], bl[8][2];
            #pragma unroll
            for (int mt = 0; mt < 2; mt++) {
                int r = wm * 32 + mt * 16 + lr;
                const char* p  = At  + r * ROW_BYTES + (ks + lc) * 2;
                const char* p2 = Alt + r * ROW_BYTES + (ks + lc) * 2;
                ah[mt][0] = *(const uint32_t*)p;
                ah[mt][1] = *(const uint32_t*)(p + 8 * ROW_BYTES);
                ah[mt][2] = *(const uint32_t*)(p + 16);
                ah[mt][3] = *(const uint32_t*)(p + 8 * ROW_BYTES + 16);
                al[mt][0] = *(const uint32_t*)p2;
                al[mt][1] = *(const uint32_t*)(p2 + 8 * ROW_BYTES);
                al[mt][2] = *(const uint32_t*)(p2 + 16);
                al[mt][3] = *(const uint32_t*)(p2 + 8 * ROW_BYTES + 16);
            }
            #pragma unroll
            for (int nt = 0; nt < 8; nt++) {
                int n = wn * 64 + nt * 8 + lr;
                const char* p  = Bt  + n * ROW_BYTES + (ks + lc) * 2;
                const char* p2 = Blt + n * ROW_BYTES + (ks + lc) * 2;
                bh[nt][0] = *(const uint32_t*)p;
                bh[nt][1] = *(const uint32_t*)(p + 16);
                bl[nt][0] = *(const uint32_t*)p2;
                bl[nt][1] = *(const uint32_t*)(p2 + 16);
            }
            // term-outer order: consecutive MMAs hit different accumulators
            #pragma unroll
            for (int mt = 0; mt < 2; mt++)
                #pragma unroll
                for (int nt = 0; nt < 8; nt++) MMA16816(acc[mt][nt], ah[mt], bh[nt]);
            #pragma unroll
            for (int mt = 0; mt < 2; mt++)
                #pragma unroll
                for (int nt = 0; nt < 8; nt++) MMA16816(acc[mt][nt], ah[mt], bl[nt]);
            #pragma unroll
            for (int mt = 0; mt < 2; mt++)
                #pragma unroll
                for (int nt = 0; nt < 8; nt++) MMA16816(acc[mt][nt], al[mt], bh[nt]);
        }
        __syncthreads();
    }

    // ---- epilogue -----------------------------------------------------------
    #pragma unroll
    for (int mt = 0; mt < 2; mt++) {
        int r0 = brow + wm * 32 + mt * 16 + lr;
        #pragma unroll
        for (int nt = 0; nt < 8; nt++) {
            int cc = bcol + wn * 64 + nt * 8 + lc;
            float bv0 = 0.0f, bv1 = 0.0f;
            if (flags & 1) { bv0 = bias[cc]; bv1 = bias[cc + 1]; }
            #pragma unroll
            for (int half = 0; half < 2; half++) {
                int r = r0 + half * 8;
                if (r < M) {
                    float v0 = acc[mt][nt][half * 2 + 0] + bv0;
                    float v1 = acc[mt][nt][half * 2 + 1] + bv1;
                    if (flags & 2) {
                        v0 = 0.5f * v0 * (1.0f + erff(v0 * 0.70710678118654752440f));
                        v1 = 0.5f * v1 * (1.0f + erff(v1 * 0.70710678118654752440f));
                    }
                    *(float2*)(C + (size_t)r * ldc + cc) = make_float2(v0, v1);
                }
            }
        }
    }
}

// ============================================================================
// mask parse / im2col / patch epilogue
// ============================================================================
__global__ void mask_kernel(const unsigned char* __restrict__ mp)
{
    __shared__ int s_type;
    int tid = threadIdx.x;
    if (tid == 0) {
        bool big = false, misal = false;
        for (int i = 0; i < BATCH * N_TOK; i++) {
            unsigned char v = mp[i];
            if (v >= 2) big = true;
            else if (v && (i & 3)) misal = true;
        }
        s_type = big ? 2 : (misal ? 1 : 0);
    }
    __syncthreads();
    int type = s_type;
    int b = tid;
    if (b < BATCH) {
        int cnt = 0;
        for (int t = 0; t < N_TOK; t++) {
            int idx = b * N_TOK + t;
            bool m;
            if (type == 2)      m = (((const float*)mp)[idx] != 0.0f);
            else if (type == 1) m = (mp[idx] != 0);
            else                m = (((const int*)mp)[idx] != 0);
            if (m) { g_order[b * N_TOK + cnt] = t; cnt++; }
        }
        g_len[b] = cnt;
    }
}

__global__ void im2col_kernel(const float* __restrict__ x, int Sc)
{
    int s = blockIdx.x, b = blockIdx.y;
    int m = b * Sc + s;
    float* dst = g_im2col + (size_t)m * D_MODEL;
    if (s >= g_len[b]) {
        for (int k = threadIdx.x; k < D_MODEL; k += blockDim.x) dst[k] = 0.0f;
        return;
    }
    int t = g_order[b * N_TOK + s];
    int gy = t / 14, gx = t % 14;
    const float* xb = x + (size_t)b * 3 * 224 * 224;
    for (int k = threadIdx.x; k < D_MODEL; k += blockDim.x) {
        int c = k >> 8, r = (k >> 4) & 15, cc = k & 15;
        dst[k] = xb[((size_t)c * 224 + (gy * 16 + r)) * 224 + (gx * 16 + cc)];
    }
}

__global__ void patch_epi_kernel(const float* __restrict__ pb,
                                 const float* __restrict__ pos, int Sc)
{
    int s = blockIdx.x, b = blockIdx.y;
    int m = b * Sc + s;
    float* row = g_X + (size_t)m * D_MODEL;
    if (s >= g_len[b]) {
        for (int d = threadIdx.x; d < D_MODEL; d += blockDim.x) row[d] = 0.0f;
        return;
    }
    int t = g_order[b * N_TOK + s];
    const float* pr = pos + (size_t)t * D_MODEL;
    for (int d = threadIdx.x; d < D_MODEL; d += blockDim.x)
        row[d] = row[d] + pb[d] + pr[d];
}

// ============================================================================
// attention (fp32 SIMT)
// ============================================================================
__global__ void scores_kernel(int Sc)
{
    int bh = blockIdx.z;
    int b = bh / N_HEADS, h = bh % N_HEADS;
    int q0 = blockIdx.y * 16, k0 = blockIdx.x * 16;
    __shared__ float qs[16][65], ks[16][65];
    int tx = threadIdx.x, ty = threadIdx.y;
    {
        int q = q0 + ty;
        if (q < Sc) {
            const float* qp = g_qkv + ((size_t)(b * Sc + q)) * (3 * D_MODEL) + h * HEAD_DIM;
            for (int j = tx; j < HEAD_DIM; j += 16) qs[ty][j] = qp[j];
        } else for (int j = tx; j < HEAD_DIM; j += 16) qs[ty][j] = 0.0f;
        int k = k0 + ty;
        if (k < Sc) {
            const float* kp = g_qkv + ((size_t)(b * Sc + k)) * (3 * D_MODEL) + D_MODEL + h * HEAD_DIM;
            for (int j = tx; j < HEAD_DIM; j += 16) ks[ty][j] = kp[j];
        } else for (int j = tx; j < HEAD_DIM; j += 16) ks[ty][j] = 0.0f;
    }
    __syncthreads();
    int q = q0 + ty, k = k0 + tx;
    if (q < Sc && k < Sc) {
        float acc = 0.0f;
        #pragma unroll
        for (int j = 0; j < HEAD_DIM; j++) acc += qs[ty][j] * ks[tx][j];
        acc *= 0.125f;
        if (k >= g_len[b]) acc = -1e30f;
        g_scores[((size_t)bh * Sc + q) * Sc + k] = acc;
    }
}

__global__ void softmax_kernel(int Sc)
{
    int q = blockIdx.x, bh = blockIdx.y;
    float* row = g_scores + ((size_t)bh * Sc + q) * Sc;
    int tid = threadIdx.x;
    __shared__ float sh[4], sh2[4];
    float mx = -3.4e38f;
    for (int i = tid; i < Sc; i += 128) mx = fmaxf(mx, row[i]);
    #pragma unroll
    for (int o = 16; o; o >>= 1) mx = fmaxf(mx, __shfl_down_sync(0xffffffffu, mx, o));
    if ((tid & 31) == 0) sh[tid >> 5] = mx;
    __syncthreads();
    mx = fmaxf(fmaxf(sh[0], sh[1]), fmaxf(sh[2], sh[3]));
    float sum = 0.0f;
    for (int i = tid; i < Sc; i += 128) {
        float e = __expf(row[i] - mx);
        row[i] = e;
        sum += e;
    }
    #pragma unroll
    for (int o = 16; o; o >>= 1) sum += __shfl_down_sync(0xffffffffu, sum, o);
    if ((tid & 31) == 0) sh2[tid >> 5] = sum;
    __syncthreads();
    sum = sh2[0] + sh2[1] + sh2[2] + sh2[3];
    float inv = 1.0f / sum;
    for (int i = tid; i < Sc; i += 128) row[i] *= inv;
}

__global__ void pv_kernel(int Sc)
{
    int bh = blockIdx.z;
    int b = bh / N_HEADS, h = bh % N_HEADS;
    int q0 = blockIdx.y * 16, j0 = blockIdx.x * 16;
    __shared__ float ps[16][17], vs[16][17];
    int tx = threadIdx.x, ty = threadIdx.y;
    float acc = 0.0f;
    for (int kk0 = 0; kk0 < Sc; kk0 += 16) {
        int q = q0 + ty, k = kk0 + tx;
        ps[ty][tx] = (q < Sc && k < Sc) ? g_scores[((size_t)bh * Sc + q) * Sc + k] : 0.0f;
        int kv = kk0 + ty;
        vs[ty][tx] = (kv < Sc)
            ? g_qkv[((size_t)(b * Sc + kv)) * (3 * D_MODEL) + 2 * D_MODEL + h * HEAD_DIM + j0 + tx]
            : 0.0f;
        __syncthreads();
        #pragma unroll
        for (int kk = 0; kk < 16; kk++) acc += ps[ty][kk] * vs[kk][tx];
        __syncthreads();
    }
    int q = q0 + ty;
    if (q < Sc)
        g_attn[((size_t)(b * Sc + q)) * D_MODEL + h * HEAD_DIM + j0 + tx] = acc;
}

// ============================================================================
// LayerNorm
// ============================================================================
__device__ __forceinline__ float blockReduce256(float v)
{
    __shared__ float sh[8];
    __syncthreads();
    #pragma unroll
    for (int o = 16; o; o >>= 1) v += __shfl_down_sync(0xffffffffu, v, o);
    if ((threadIdx.x & 31) == 0) sh[threadIdx.x >> 5] = v;
    __syncthreads();
    return sh[0] + sh[1] + sh[2] + sh[3] + sh[4] + sh[5] + sh[6] + sh[7];
}

template<bool RESID>
__global__ void ln_kernel(const float* __restrict__ X, const float* __restrict__ Rsd,
                          const float* __restrict__ gma, const float* __restrict__ bta,
                          float* __restrict__ out)
{
    int m = blockIdx.x;
    int tid = threadIdx.x;
    const float* xr = X + (size_t)m * D_MODEL;
    float v[3];
    #pragma unroll
    for (int i = 0; i < 3; i++) {
        int d = tid + 256 * i;
        v[i] = xr[d];
        if (RESID) v[i] += Rsd[(size_t)m * D_MODEL + d];
    }
    float s = blockReduce256(v[0] + v[1] + v[2]);
    float mean = s * (1.0f / 768.0f);
    float q = 0.0f;
    #pragma unroll
    for (int i = 0; i < 3; i++) { float d = v[i] - mean; q += d * d; }
    q = blockReduce256(q);
    float inv = 1.0f / sqrtf(q * (1.0f / 768.0f) + 1e-5f);
    float* orow = out + (size_t)m * D_MODEL;
    #pragma unroll
    for (int i = 0; i < 3; i++) {
        int d = tid + 256 * i;
        orow[d] = (v[i] - mean) * inv * gma[d] + bta[d];
    }
}

__global__ void pad_out_kernel(float* __restrict__ out2, int Sc)
{
    int i = blockIdx.x * blockDim.x + threadIdx.x;
    if (i < BATCH * Sc) {
        int b = i / Sc, s = i % Sc;
        out2[i] = (s >= g_len[b]) ? 1.0f : 0.0f;
    }
}

// ===========================================================================
static void run_split(const float* src, __nv_bfloat16* hi, __nv_bfloat16* lo, size_t n)
{
    int n4 = (int)(n >> 2);
    split_kernel<<<(n4 + 255) / 256, 256>>>((const float4*)src, (uint2*)hi, (uint2*)lo, n4);
}

extern "C" void kernel_launch(void* const* d_in, const int* in_sizes, int n_in,
                              void* d_out, int out_size)
{
    const float* x       = (const float*)d_in[0];
    const void*  mask    = d_in[1];
    const float* patch_w = (const float*)d_in[2];
    const float* patch_b = (const float*)d_in[3];
    const float* pos     = (const float*)d_in[4];
    const float* inw     = (const float*)d_in[5];
    const float* inb     = (const float*)d_in[6];
    const float* outw    = (const float*)d_in[7];
    const float* outb    = (const float*)d_in[8];
    const float* ln1g    = (const float*)d_in[9];
    const float* ln1b    = (const float*)d_in[10];
    const float* f1w     = (const float*)d_in[11];
    const float* f1b     = (const float*)d_in[12];
    const float* f2w     = (const float*)d_in[13];
    const float* f2b     = (const float*)d_in[14];
    const float* ln2g    = (const float*)d_in[15];
    const float* ln2b    = (const float*)d_in[16];
    const float* ng      = (const float*)d_in[17];
    const float* nb      = (const float*)d_in[18];

    int Sc; bool tup;
    if (out_size % (64 * 769) == 0 &&
        out_size / (64 * 769) >= 1 && out_size / (64 * 769) <= N_TOK) {
        Sc = out_size / (64 * 769); tup = true;
    } else {
        Sc = out_size / (64 * 768); tup = false;
    }
    if (Sc < 1) Sc = 1;
    if (Sc > N_TOK) Sc = N_TOK;
    const int M  = BATCH * Sc;
    const int MB = (M + 127) / 128;
    const int ST = (Sc + 15) / 16;

    float *pIm, *pX, *pQ, *pA, *pP, *pF;
    __nv_bfloat16 *ah, *al, *wqh, *wql, *woh, *wol, *w1h, *w1l, *w2h, *w2l, *wph, *wpl;
    cudaGetSymbolAddress((void**)&pIm, g_im2col);
    cudaGetSymbolAddress((void**)&pX,  g_X);
    cudaGetSymbolAddress((void**)&pQ,  g_qkv);
    cudaGetSymbolAddress((void**)&pA,  g_attn);
    cudaGetSymbolAddress((void**)&pP,  g_proj);
    cudaGetSymbolAddress((void**)&pF,  g_ffn);
    cudaGetSymbolAddress((void**)&ah,  g_ah);
    cudaGetSymbolAddress((void**)&al,  g_al);
    cudaGetSymbolAddress((void**)&wqh, g_wqkv_h);
    cudaGetSymbolAddress((void**)&wql, g_wqkv_l);
    cudaGetSymbolAddress((void**)&woh, g_wo_h);
    cudaGetSymbolAddress((void**)&wol, g_wo_l);
    cudaGetSymbolAddress((void**)&w1h, g_wf1_h);
    cudaGetSymbolAddress((void**)&w1l, g_wf1_l);
    cudaGetSymbolAddress((void**)&w2h, g_wf2_h);
    cudaGetSymbolAddress((void**)&w2l, g_wf2_l);
    cudaGetSymbolAddress((void**)&wph, g_wp_h);
    cudaGetSymbolAddress((void**)&wpl, g_wp_l);

    cudaFuncSetAttribute(mma_gemm_kernel, cudaFuncAttributeMaxDynamicSharedMemorySize,
                         GEMM_SMEM);

    // --- weight splits --------------------------------------------------------
    run_split(inw,     wqh, wql, (size_t)N_LAYERS * 3 * D_MODEL * D_MODEL);
    run_split(outw,    woh, wol, (size_t)N_LAYERS * D_MODEL * D_MODEL);
    run_split(f1w,     w1h, w1l, (size_t)N_LAYERS * FF_DIM * D_MODEL);
    run_split(f2w,     w2h, w2l, (size_t)N_LAYERS * FF_DIM * D_MODEL);
    run_split(patch_w, wph, wpl, (size_t)D_MODEL * D_MODEL);

    // --- mask parse + gather + patch embedding --------------------------------
    mask_kernel<<<1, 64>>>((const unsigned char*)mask);
    im2col_kernel<<<dim3(Sc, BATCH), 256>>>(x, Sc);
    run_split(pIm, ah, al, (size_t)M * D_MODEL);
    mma_gemm_kernel<<<dim3(6, MB), 256, GEMM_SMEM>>>(
        ah, al, wph, wpl, nullptr, pX, D_MODEL, M, D_MODEL, 0);
    patch_epi_kernel<<<dim3(Sc, BATCH), 256>>>(patch_b, pos, Sc);

    // --- transformer layers ---------------------------------------------------
    for (int l = 0; l < N_LAYERS; l++) {
        const __nv_bfloat16* Wqh = wqh + (size_t)l * 3 * D_MODEL * D_MODEL;
        const __nv_bfloat16* Wql = wql + (size_t)l * 3 * D_MODEL * D_MODEL;
        const __nv_bfloat16* Woh = woh + (size_t)l * D_MODEL * D_MODEL;
        const __nv_bfloat16* Wol = wol + (size_t)l * D_MODEL * D_MODEL;
        const __nv_bfloat16* W1h = w1h + (size_t)l * FF_DIM * D_MODEL;
        const __nv_bfloat16* W1l = w1l + (size_t)l * FF_DIM * D_MODEL;
        const __nv_bfloat16* W2h = w2h + (size_t)l * FF_DIM * D_MODEL;
        const __nv_bfloat16* W2l = w2l + (size_t)l * FF_DIM * D_MODEL;
        const float* bqkv = inb  + (size_t)l * 3 * D_MODEL;
        const float* bo   = outb + (size_t)l * D_MODEL;
        const float* b1   = f1b  + (size_t)l * FF_DIM;
        const float* b2   = f2b  + (size_t)l * D_MODEL;

        // QKV projection
        run_split(pX, ah, al, (size_t)M * D_MODEL);
        mma_gemm_kernel<<<dim3(18, MB), 256, GEMM_SMEM>>>(
            ah, al, Wqh, Wql, bqkv, pQ, 3 * D_MODEL, M, D_MODEL, 1);
        // attention
        scores_kernel <<<dim3(ST, ST, BATCH * N_HEADS), dim3(16, 16)>>>(Sc);
        softmax_kernel<<<dim3(Sc, BATCH * N_HEADS), 128>>>(Sc);
        pv_kernel     <<<dim3(4, ST, BATCH * N_HEADS), dim3(16, 16)>>>(Sc);
        // output projection
        run_split(pA, ah, al, (size_t)M * D_MODEL);
        mma_gemm_kernel<<<dim3(6, MB), 256, GEMM_SMEM>>>(
            ah, al, Woh, Wol, bo, pP, D_MODEL, M, D_MODEL, 1);
        // residual + LN1
        ln_kernel<true><<<M, 256>>>(pX, pP, ln1g + l * D_MODEL, ln1b + l * D_MODEL, pX);
        // FFN1 (+GELU)
        run_split(pX, ah, al, (size_t)M * D_MODEL);
        mma_gemm_kernel<<<dim3(24, MB), 256, GEMM_SMEM>>>(
            ah, al, W1h, W1l, b1, pF, FF_DIM, M, D_MODEL, 3);
        // FFN2
        run_split(pF, ah, al, (size_t)M * FF_DIM);
        mma_gemm_kernel<<<dim3(6, MB), 256, GEMM_SMEM>>>(
            ah, al, W2h, W2l, b2, pP, D_MODEL, M, FF_DIM, 1);
        // residual + LN2
        ln_kernel<true><<<M, 256>>>(pX, pP, ln2g + l * D_MODEL, ln2b + l * D_MODEL, pX);
    }

    // --- final LN into d_out --------------------------------------------------
    ln_kernel<false><<<M, 256>>>(pX, nullptr, ng, nb, (float*)d_out);
    if (tup) {
        pad_out_kernel<<<(BATCH * Sc + 255) / 256, 256>>>(
            (float*)d_out + (size_t)M * D_MODEL, Sc);
    }
}

// round 4
// speedup vs baseline: 4.1758x; 1.2584x over previous
#include <cuda_runtime.h>
#include <cuda_fp16.h>
#include <math.h>
#include <stdint.h>

// ============================================================================
// Masked ViT context encoder. R4: fp16 3-term split GEMM with ldmatrix,
// fused flash attention (fp32), splits fused into producer epilogues.
// ============================================================================

#define BATCH    64
#define N_TOK    196
#define D_MODEL  768
#define N_HEADS  12
#define HEAD_DIM 64
#define N_LAYERS 12
#define FF_DIM   3072
#define M_MAX    (BATCH * N_TOK)

// ---------------- scratch (device globals; no allocation allowed) -----------
__device__ int    g_order[BATCH * N_TOK];
__device__ int    g_len[BATCH];
__device__ float  g_X[(size_t)M_MAX * D_MODEL];
__device__ float  g_qkv[(size_t)M_MAX * 3 * D_MODEL];
__device__ float  g_proj[(size_t)M_MAX * D_MODEL];
// fp16 hi/lo activation buffers
__device__ __half g_ah[(size_t)M_MAX * D_MODEL];
__device__ __half g_al[(size_t)M_MAX * D_MODEL];
__device__ __half g_fh[(size_t)M_MAX * FF_DIM];
__device__ __half g_fl[(size_t)M_MAX * FF_DIM];
// fp16 hi/lo weights
__device__ __half g_wqkv_h[(size_t)N_LAYERS * 3 * D_MODEL * D_MODEL];
__device__ __half g_wqkv_l[(size_t)N_LAYERS * 3 * D_MODEL * D_MODEL];
__device__ __half g_wo_h[(size_t)N_LAYERS * D_MODEL * D_MODEL];
__device__ __half g_wo_l[(size_t)N_LAYERS * D_MODEL * D_MODEL];
__device__ __half g_wf1_h[(size_t)N_LAYERS * FF_DIM * D_MODEL];
__device__ __half g_wf1_l[(size_t)N_LAYERS * FF_DIM * D_MODEL];
__device__ __half g_wf2_h[(size_t)N_LAYERS * FF_DIM * D_MODEL];
__device__ __half g_wf2_l[(size_t)N_LAYERS * FF_DIM * D_MODEL];
__device__ __half g_wp_h[(size_t)D_MODEL * D_MODEL];
__device__ __half g_wp_l[(size_t)D_MODEL * D_MODEL];

// ============================================================================
// helpers
// ============================================================================
__device__ __forceinline__ uint32_t smem_u32(const void* p) {
    uint32_t a;
    asm("{ .reg .u64 t; cvta.to.shared.u64 t, %1; cvt.u32.u64 %0, t; }"
        : "=r"(a) : "l"(p));
    return a;
}
__device__ __forceinline__ void split_hl(float v, __half& h, __half& l) {
    h = __float2half(v);
    l = __float2half(v - __half2float(h));
}

#define CP_ASYNC_16(dst, src) \
    asm volatile("cp.async.cg.shared.global [%0], [%1], 16;" :: "r"(dst), "l"(src))
#define CP_COMMIT() asm volatile("cp.async.commit_group;" ::: "memory")
#define CP_WAIT(n)  asm volatile("cp.async.wait_group %0;" :: "n"(n) : "memory")

#define LDSM4(r0, r1, r2, r3, addr) \
    asm volatile("ldmatrix.sync.aligned.m8n8.x4.shared.b16 {%0,%1,%2,%3}, [%4];" \
        : "=r"(r0), "=r"(r1), "=r"(r2), "=r"(r3) : "r"(addr))

#define MMA16816(c, a, b) \
    asm volatile("mma.sync.aligned.m16n8k16.row.col.f32.f16.f16.f32 " \
        "{%0,%1,%2,%3}, {%4,%5,%6,%7}, {%8,%9}, {%0,%1,%2,%3};" \
        : "+f"((c)[0]), "+f"((c)[1]), "+f"((c)[2]), "+f"((c)[3]) \
        : "r"((a)[0]), "r"((a)[1]), "r"((a)[2]), "r"((a)[3]), \
          "r"((b)[0]), "r"((b)[1]))

// ============================================================================
// weight split: fp32 -> (hi fp16, lo fp16)
// ============================================================================
__global__ void split_kernel(const float4* __restrict__ src,
                             __half2* __restrict__ hi, __half2* __restrict__ lo, int n4)
{
    int i = blockIdx.x * blockDim.x + threadIdx.x;
    if (i >= n4) return;
    float4 v = src[i];
    __half h0, h1, h2, h3, l0, l1, l2, l3;
    split_hl(v.x, h0, l0); split_hl(v.y, h1, l1);
    split_hl(v.z, h2, l2); split_hl(v.w, h3, l3);
    hi[i * 2 + 0] = __halves2half2(h0, h1);
    hi[i * 2 + 1] = __halves2half2(h2, h3);
    lo[i * 2 + 0] = __halves2half2(l0, l1);
    lo[i * 2 + 1] = __halves2half2(l2, l3);
}

// ============================================================================
// HMMA GEMM (fp16 3-term): C = (Ah+Al)(Bh+Bl)^T, AlBl dropped.
// 128x128 CTA tile, K-chunk 64, cp.async double buffer, ldmatrix fragments,
// 8 warps (4m x 2n), warp tile 32x64 (2 x 8 m16n8k16).
// flags: bit0 bias, bit1 exact GELU, bit2 write fp16 h/l (Ch/Cl) else fp32 C.
// ============================================================================
#define ROW_BYTES   144                 // 64 fp16 (128B) + 16B pad
#define TILE_BYTES  (128 * ROW_BYTES)   // 18432
#define STAGE_BYTES (4 * TILE_BYTES)    // 73728
#define GEMM_SMEM   (2 * STAGE_BYTES)   // 147456

__global__ void __launch_bounds__(256, 1)
mma_gemm_kernel(const __half* __restrict__ Ah, const __half* __restrict__ Al,
                const __half* __restrict__ Bh, const __half* __restrict__ Bl,
                const float* __restrict__ bias,
                float* __restrict__ C, __half* __restrict__ Ch, __half* __restrict__ Cl,
                int ldc, int M, int K, int flags)
{
    extern __shared__ char smem[];
    const uint32_t sb = smem_u32(smem);
    const int tid  = threadIdx.x;
    const int wid  = tid >> 5, lane = tid & 31;
    const int wm   = wid & 3, wn = wid >> 2;
    const int brow = blockIdx.y * 128;
    const int bcol = blockIdx.x * 128;

    float acc[2][8][4];
    #pragma unroll
    for (int mt = 0; mt < 2; mt++)
        #pragma unroll
        for (int nt = 0; nt < 8; nt++)
            #pragma unroll
            for (int i = 0; i < 4; i++) acc[mt][nt][i] = 0.0f;

    const int nC = K >> 6;

    auto load_chunk = [&](int c, int buf) {
        const int k0 = c << 6;
        const uint32_t tb = sb + (uint32_t)buf * STAGE_BYTES;
        #pragma unroll
        for (int j = 0; j < 16; j++) {
            int idx = tid + (j << 8);
            int op  = idx >> 10;          // 0=Ah 1=Al 2=Bh 3=Bl
            int rem = idx & 1023;
            int r   = rem >> 3;           // row 0..127
            int q   = rem & 7;            // 16B chunk (8 halves)
            const __half* gp;
            if (op < 2) {
                int gr = brow + r;
                if (gr >= M) gr = M - 1;
                gp = (op ? Al : Ah) + (size_t)gr * K + k0 + (q << 3);
            } else {
                int gn = bcol + r;
                gp = (op == 3 ? Bl : Bh) + (size_t)gn * K + k0 + (q << 3);
            }
            uint32_t dst = tb + (uint32_t)op * TILE_BYTES + (uint32_t)r * ROW_BYTES + (q << 4);
            CP_ASYNC_16(dst, gp);
        }
        CP_COMMIT();
    };

    load_chunk(0, 0);

    // precomputed intra-tile ldmatrix offsets
    const uint32_t a_off = (uint32_t)(wm * 32 + (lane & 15)) * ROW_BYTES
                         + (uint32_t)((lane >> 4) << 3) * 2;           // + ks*2
    const int   b_mm  = lane >> 3;           // matrix 0..3
    const uint32_t b_row_off = (uint32_t)(wn * 64 + ((b_mm >> 1) << 3) + (lane & 7)) * ROW_BYTES;
    const uint32_t b_k_off   = (uint32_t)((b_mm & 1) << 3) * 2;        // + ks*2

    for (int c = 0; c < nC; c++) {
        const int buf = c & 1;
        if (c + 1 < nC) { load_chunk(c + 1, buf ^ 1); CP_WAIT(1); }
        else            { CP_WAIT(0); }
        __syncthreads();

        const uint32_t At  = sb + (uint32_t)buf * STAGE_BYTES;
        const uint32_t Alt = At + TILE_BYTES;
        const uint32_t Bt  = At + 2 * TILE_BYTES;
        const uint32_t Blt = At + 3 * TILE_BYTES;

        #pragma unroll
        for (int ks = 0; ks < 64; ks += 16) {
            uint32_t ah[2][4], al[2][4], bh[8][2], bl[8][2];
            const uint32_t ksb = (uint32_t)ks * 2;
            LDSM4(ah[0][0], ah[0][1], ah[0][2], ah[0][3], At  + a_off + ksb);
            LDSM4(ah[1][0], ah[1][1], ah[1][2], ah[1][3], At  + a_off + ksb + 16 * ROW_BYTES);
            LDSM4(al[0][0], al[0][1], al[0][2], al[0][3], Alt + a_off + ksb);
            LDSM4(al[1][0], al[1][1], al[1][2], al[1][3], Alt + a_off + ksb + 16 * ROW_BYTES);
            #pragma unroll
            for (int g = 0; g < 4; g++) {
                uint32_t off = b_row_off + (uint32_t)(g * 16) * ROW_BYTES + b_k_off + ksb;
                LDSM4(bh[2*g][0], bh[2*g][1], bh[2*g+1][0], bh[2*g+1][1], Bt  + off);
                LDSM4(bl[2*g][0], bl[2*g][1], bl[2*g+1][0], bl[2*g+1][1], Blt + off);
            }
            #pragma unroll
            for (int mt = 0; mt < 2; mt++)
                #pragma unroll
                for (int nt = 0; nt < 8; nt++) MMA16816(acc[mt][nt], ah[mt], bh[nt]);
            #pragma unroll
            for (int mt = 0; mt < 2; mt++)
                #pragma unroll
                for (int nt = 0; nt < 8; nt++) MMA16816(acc[mt][nt], ah[mt], bl[nt]);
            #pragma unroll
            for (int mt = 0; mt < 2; mt++)
                #pragma unroll
                for (int nt = 0; nt < 8; nt++) MMA16816(acc[mt][nt], al[mt], bh[nt]);
        }
        __syncthreads();
    }

    // ---- epilogue -----------------------------------------------------------
    const int lr = lane >> 2, lc = (lane & 3) * 2;
    #pragma unroll
    for (int mt = 0; mt < 2; mt++) {
        int r0 = brow + wm * 32 + mt * 16 + lr;
        #pragma unroll
        for (int nt = 0; nt < 8; nt++) {
            int cc = bcol + wn * 64 + nt * 8 + lc;
            float bv0 = 0.0f, bv1 = 0.0f;
            if (flags & 1) { bv0 = bias[cc]; bv1 = bias[cc + 1]; }
            #pragma unroll
            for (int half = 0; half < 2; half++) {
                int r = r0 + half * 8;
                if (r < M) {
                    float v0 = acc[mt][nt][half * 2 + 0] + bv0;
                    float v1 = acc[mt][nt][half * 2 + 1] + bv1;
                    if (flags & 2) {
                        v0 = 0.5f * v0 * (1.0f + erff(v0 * 0.70710678118654752440f));
                        v1 = 0.5f * v1 * (1.0f + erff(v1 * 0.70710678118654752440f));
                    }
                    if (flags & 4) {
                        __half h0, h1, l0, l1;
                        split_hl(v0, h0, l0); split_hl(v1, h1, l1);
                        *(__half2*)(Ch + (size_t)r * ldc + cc) = __halves2half2(h0, h1);
                        *(__half2*)(Cl + (size_t)r * ldc + cc) = __halves2half2(l0, l1);
                    } else {
                        *(float2*)(C + (size_t)r * ldc + cc) = make_float2(v0, v1);
                    }
                }
            }
        }
    }
}

// ============================================================================
// mask parse (parallel detection)
// ============================================================================
__global__ void mask_kernel(const unsigned char* __restrict__ mp)
{
    int tid = threadIdx.x;   // 256
    bool big = false, misal = false;
    for (int i = tid; i < BATCH * N_TOK; i += 256) {
        unsigned char v = mp[i];
        if (v >= 2) big = true;
        else if (v && (i & 3)) misal = true;
    }
    int anybig = __syncthreads_or(big ? 1 : 0);
    int anymis = __syncthreads_or(misal ? 1 : 0);
    int type = anybig ? 2 : (anymis ? 1 : 0);
    int b = tid;
    if (b < BATCH) {
        int cnt = 0;
        for (int t = 0; t < N_TOK; t++) {
            int idx = b * N_TOK + t;
            bool m;
            if (type == 2)      m = (((const float*)mp)[idx] != 0.0f);
            else if (type == 1) m = (mp[idx] != 0);
            else                m = (((const int*)mp)[idx] != 0);
            if (m) { g_order[b * N_TOK + cnt] = t; cnt++; }
        }
        g_len[b] = cnt;
    }
}

// ============================================================================
// im2col gather, writing fp16 h/l directly (patch GEMM inputs)
// ============================================================================
__global__ void im2col_kernel(const float* __restrict__ x, int Sc)
{
    int s = blockIdx.x, b = blockIdx.y;
    int m = b * Sc + s;
    __half* dh = g_ah + (size_t)m * D_MODEL;
    __half* dl = g_al + (size_t)m * D_MODEL;
    if (s >= g_len[b]) {
        for (int k = threadIdx.x; k < D_MODEL; k += blockDim.x) {
            dh[k] = __float2half(0.0f); dl[k] = __float2half(0.0f);
        }
        return;
    }
    int t = g_order[b * N_TOK + s];
    int gy = t / 14, gx = t % 14;
    const float* xb = x + (size_t)b * 3 * 224 * 224;
    for (int k = threadIdx.x; k < D_MODEL; k += blockDim.x) {
        int c = k >> 8, r = (k >> 4) & 15, cc = k & 15;
        float v = xb[((size_t)c * 224 + (gy * 16 + r)) * 224 + (gx * 16 + cc)];
        __half h, l; split_hl(v, h, l);
        dh[k] = h; dl[k] = l;
    }
}

// patch epilogue: X += patch_b + pos; emit h/l for QKV GEMM; zero pad rows.
__global__ void patch_epi_kernel(const float* __restrict__ pb,
                                 const float* __restrict__ pos, int Sc)
{
    int s = blockIdx.x, b = blockIdx.y;
    int m = b * Sc + s;
    float* row = g_X + (size_t)m * D_MODEL;
    __half* dh = g_ah + (size_t)m * D_MODEL;
    __half* dl = g_al + (size_t)m * D_MODEL;
    if (s >= g_len[b]) {
        for (int d = threadIdx.x; d < D_MODEL; d += blockDim.x) {
            row[d] = 0.0f;
            dh[d] = __float2half(0.0f); dl[d] = __float2half(0.0f);
        }
        return;
    }
    int t = g_order[b * N_TOK + s];
    const float* pr = pos + (size_t)t * D_MODEL;
    for (int d = threadIdx.x; d < D_MODEL; d += blockDim.x) {
        float v = row[d] + pb[d] + pr[d];
        row[d] = v;
        __half h, l; split_hl(v, h, l);
        dh[d] = h; dl[d] = l;
    }
}

// ============================================================================
// Fused flash attention (fp32), one CTA per (b,h). Whole Q/K/V in SMEM.
// Output written as fp16 h/l (proj GEMM inputs).
// ============================================================================
#define KS_STRIDE 65

__global__ void __launch_bounds__(256, 1)
flash_kernel(int Sc)
{
    extern __shared__ float fs[];
    float* qs = fs;                       // [Sc][64]
    float* ks = qs + Sc * 64;             // [Sc][65]
    float* vs = ks + Sc * KS_STRIDE;      // [Sc][64]
    float* es = vs + Sc * 64;             // [8][32]

    const int b = blockIdx.x / N_HEADS, h = blockIdx.x % N_HEADS;
    const int len = g_len[b];
    const int tid = threadIdx.x, lane = tid & 31, wid = tid >> 5;
    const size_t base = (size_t)(b * Sc) * (3 * D_MODEL) + h * HEAD_DIM;

    for (int idx = tid; idx < Sc * 64; idx += 256) {
        int r = idx >> 6, d = idx & 63;
        size_t g = base + (size_t)r * (3 * D_MODEL) + d;
        qs[idx] = g_qkv[g];
        ks[r * KS_STRIDE + d] = g_qkv[g + D_MODEL];
        vs[idx] = g_qkv[g + 2 * D_MODEL];
    }
    __syncthreads();

    float* ew = es + wid * 32;
    for (int q = wid; q < Sc; q += 8) {
        const float* qrow = qs + q * 64;
        float m = -3.4e38f, l = 0.0f;
        float o0a = 0.f, o0b = 0.f, o1a = 0.f, o1b = 0.f;
        for (int j0 = 0; j0 < len; j0 += 32) {
            int j = j0 + lane;
            int jj = (j < len) ? j : (len - 1);
            const float* krow = ks + jj * KS_STRIDE;
            float s0 = 0.f, s1 = 0.f, s2 = 0.f, s3 = 0.f;
            #pragma unroll
            for (int d = 0; d < 64; d += 4) {
                s0 += qrow[d + 0] * krow[d + 0];
                s1 += qrow[d + 1] * krow[d + 1];
                s2 += qrow[d + 2] * krow[d + 2];
                s3 += qrow[d + 3] * krow[d + 3];
            }
            float s = ((s0 + s1) + (s2 + s3)) * 0.125f;
            if (j >= len) s = -3.4e38f;
            float tmax = s;
            #pragma unroll
            for (int o = 16; o; o >>= 1) tmax = fmaxf(tmax, __shfl_xor_sync(0xffffffffu, tmax, o));
            float mnew = fmaxf(m, tmax);
            float scale = __expf(m - mnew);
            float e = (j < len) ? __expf(s - mnew) : 0.0f;
            float esum = e;
            #pragma unroll
            for (int o = 16; o; o >>= 1) esum += __shfl_xor_sync(0xffffffffu, esum, o);
            l = l * scale + esum;
            m = mnew;
            o0a *= scale; o0b *= scale; o1a *= scale; o1b *= scale;
            ew[lane] = e;
            __syncwarp();
            int jmax = (len - j0 < 32) ? (len - j0) : 32;
            int j2 = 0;
            for (; j2 + 2 <= jmax; j2 += 2) {
                float e0 = ew[j2], e1 = ew[j2 + 1];
                const float* v0 = vs + (j0 + j2) * 64;
                const float* v1 = v0 + 64;
                o0a += e0 * v0[lane];      o1a += e0 * v0[lane + 32];
                o0b += e1 * v1[lane];      o1b += e1 * v1[lane + 32];
            }
            if (j2 < jmax) {
                float e0 = ew[j2];
                const float* v0 = vs + (j0 + j2) * 64;
                o0a += e0 * v0[lane];      o1a += e0 * v0[lane + 32];
            }
            __syncwarp();
        }
        float inv = 1.0f / l;
        float r0 = (o0a + o0b) * inv, r1 = (o1a + o1b) * inv;
        size_t orow = (size_t)(b * Sc + q) * D_MODEL + h * HEAD_DIM;
        __half h0, l0, h1, l1;
        split_hl(r0, h0, l0); split_hl(r1, h1, l1);
        g_ah[orow + lane]      = h0;  g_al[orow + lane]      = l0;
        g_ah[orow + lane + 32] = h1;  g_al[orow + lane + 32] = l1;
    }
}

// ============================================================================
// LayerNorm (optionally +residual); optionally emits fp16 h/l alongside fp32.
// ============================================================================
__device__ __forceinline__ float blockReduce256(float v)
{
    __shared__ float sh[8];
    __syncthreads();
    #pragma unroll
    for (int o = 16; o; o >>= 1) v += __shfl_down_sync(0xffffffffu, v, o);
    if ((threadIdx.x & 31) == 0) sh[threadIdx.x >> 5] = v;
    __syncthreads();
    return sh[0] + sh[1] + sh[2] + sh[3] + sh[4] + sh[5] + sh[6] + sh[7];
}

template<bool RESID, bool EMITHL>
__global__ void ln_kernel(const float* __restrict__ X, const float* __restrict__ Rsd,
                          const float* __restrict__ gma, const float* __restrict__ bta,
                          float* __restrict__ out,
                          __half* __restrict__ outH, __half* __restrict__ outL)
{
    int m = blockIdx.x;
    int tid = threadIdx.x;
    const float* xr = X + (size_t)m * D_MODEL;
    float v[3];
    #pragma unroll
    for (int i = 0; i < 3; i++) {
        int d = tid + 256 * i;
        v[i] = xr[d];
        if (RESID) v[i] += Rsd[(size_t)m * D_MODEL + d];
    }
    float s = blockReduce256(v[0] + v[1] + v[2]);
    float mean = s * (1.0f / 768.0f);
    float q = 0.0f;
    #pragma unroll
    for (int i = 0; i < 3; i++) { float d = v[i] - mean; q += d * d; }
    q = blockReduce256(q);
    float inv = 1.0f / sqrtf(q * (1.0f / 768.0f) + 1e-5f);
    #pragma unroll
    for (int i = 0; i < 3; i++) {
        int d = tid + 256 * i;
        float r = (v[i] - mean) * inv * gma[d] + bta[d];
        out[(size_t)m * D_MODEL + d] = r;
        if (EMITHL) {
            __half h, l; split_hl(r, h, l);
            outH[(size_t)m * D_MODEL + d] = h;
            outL[(size_t)m * D_MODEL + d] = l;
        }
    }
}

__global__ void pad_out_kernel(float* __restrict__ out2, int Sc)
{
    int i = blockIdx.x * blockDim.x + threadIdx.x;
    if (i < BATCH * Sc) {
        int b = i / Sc, s = i % Sc;
        out2[i] = (s >= g_len[b]) ? 1.0f : 0.0f;
    }
}

// ===========================================================================
static void run_split(const float* src, __half* hi, __half* lo, size_t n)
{
    int n4 = (int)(n >> 2);
    split_kernel<<<(n4 + 255) / 256, 256>>>((const float4*)src, (__half2*)hi, (__half2*)lo, n4);
}

extern "C" void kernel_launch(void* const* d_in, const int* in_sizes, int n_in,
                              void* d_out, int out_size)
{
    const float* x       = (const float*)d_in[0];
    const void*  mask    = d_in[1];
    const float* patch_w = (const float*)d_in[2];
    const float* patch_b = (const float*)d_in[3];
    const float* pos     = (const float*)d_in[4];
    const float* inw     = (const float*)d_in[5];
    const float* inb     = (const float*)d_in[6];
    const float* outw    = (const float*)d_in[7];
    const float* outb    = (const float*)d_in[8];
    const float* ln1g    = (const float*)d_in[9];
    const float* ln1b    = (const float*)d_in[10];
    const float* f1w     = (const float*)d_in[11];
    const float* f1b     = (const float*)d_in[12];
    const float* f2w     = (const float*)d_in[13];
    const float* f2b     = (const float*)d_in[14];
    const float* ln2g    = (const float*)d_in[15];
    const float* ln2b    = (const float*)d_in[16];
    const float* ng      = (const float*)d_in[17];
    const float* nb      = (const float*)d_in[18];

    int Sc; bool tup;
    if (out_size % (64 * 769) == 0 &&
        out_size / (64 * 769) >= 1 && out_size / (64 * 769) <= N_TOK) {
        Sc = out_size / (64 * 769); tup = true;
    } else {
        Sc = out_size / (64 * 768); tup = false;
    }
    if (Sc < 1) Sc = 1;
    if (Sc > N_TOK) Sc = N_TOK;
    const int M  = BATCH * Sc;
    const int MB = (M + 127) / 128;
    const int flash_smem = Sc * (64 + KS_STRIDE + 64) * 4 + 8 * 32 * 4;

    float *pX, *pQ, *pP;
    __half *ah, *al, *fh, *fl, *wqh, *wql, *woh, *wol, *w1h, *w1l, *w2h, *w2l, *wph, *wpl;
    cudaGetSymbolAddress((void**)&pX,  g_X);
    cudaGetSymbolAddress((void**)&pQ,  g_qkv);
    cudaGetSymbolAddress((void**)&pP,  g_proj);
    cudaGetSymbolAddress((void**)&ah,  g_ah);
    cudaGetSymbolAddress((void**)&al,  g_al);
    cudaGetSymbolAddress((void**)&fh,  g_fh);
    cudaGetSymbolAddress((void**)&fl,  g_fl);
    cudaGetSymbolAddress((void**)&wqh, g_wqkv_h);
    cudaGetSymbolAddress((void**)&wql, g_wqkv_l);
    cudaGetSymbolAddress((void**)&woh, g_wo_h);
    cudaGetSymbolAddress((void**)&wol, g_wo_l);
    cudaGetSymbolAddress((void**)&w1h, g_wf1_h);
    cudaGetSymbolAddress((void**)&w1l, g_wf1_l);
    cudaGetSymbolAddress((void**)&w2h, g_wf2_h);
    cudaGetSymbolAddress((void**)&w2l, g_wf2_l);
    cudaGetSymbolAddress((void**)&wph, g_wp_h);
    cudaGetSymbolAddress((void**)&wpl, g_wp_l);

    cudaFuncSetAttribute(mma_gemm_kernel, cudaFuncAttributeMaxDynamicSharedMemorySize,
                         GEMM_SMEM);
    cudaFuncSetAttribute(flash_kernel, cudaFuncAttributeMaxDynamicSharedMemorySize,
                         160000);

    // --- weight splits --------------------------------------------------------
    run_split(inw,     wqh, wql, (size_t)N_LAYERS * 3 * D_MODEL * D_MODEL);
    run_split(outw,    woh, wol, (size_t)N_LAYERS * D_MODEL * D_MODEL);
    run_split(f1w,     w1h, w1l, (size_t)N_LAYERS * FF_DIM * D_MODEL);
    run_split(f2w,     w2h, w2l, (size_t)N_LAYERS * FF_DIM * D_MODEL);
    run_split(patch_w, wph, wpl, (size_t)D_MODEL * D_MODEL);

    // --- mask parse + gather + patch embedding --------------------------------
    mask_kernel<<<1, 256>>>((const unsigned char*)mask);
    im2col_kernel<<<dim3(Sc, BATCH), 256>>>(x, Sc);
    mma_gemm_kernel<<<dim3(6, MB), 256, GEMM_SMEM>>>(
        ah, al, wph, wpl, nullptr, pX, nullptr, nullptr, D_MODEL, M, D_MODEL, 0);
    patch_epi_kernel<<<dim3(Sc, BATCH), 256>>>(patch_b, pos, Sc);

    // --- transformer layers ---------------------------------------------------
    for (int l = 0; l < N_LAYERS; l++) {
        const __half* Wqh = wqh + (size_t)l * 3 * D_MODEL * D_MODEL;
        const __half* Wql = wql + (size_t)l * 3 * D_MODEL * D_MODEL;
        const __half* Woh = woh + (size_t)l * D_MODEL * D_MODEL;
        const __half* Wol = wol + (size_t)l * D_MODEL * D_MODEL;
        const __half* W1h = w1h + (size_t)l * FF_DIM * D_MODEL;
        const __half* W1l = w1l + (size_t)l * FF_DIM * D_MODEL;
        const __half* W2h = w2h + (size_t)l * FF_DIM * D_MODEL;
        const __half* W2l = w2l + (size_t)l * FF_DIM * D_MODEL;
        const float* bqkv = inb  + (size_t)l * 3 * D_MODEL;
        const float* bo   = outb + (size_t)l * D_MODEL;
        const float* b1   = f1b  + (size_t)l * FF_DIM;
        const float* b2   = f2b  + (size_t)l * D_MODEL;

        // QKV projection (reads ah/al from patch_epi or previous ln2)
        mma_gemm_kernel<<<dim3(18, MB), 256, GEMM_SMEM>>>(
            ah, al, Wqh, Wql, bqkv, pQ, nullptr, nullptr, 3 * D_MODEL, M, D_MODEL, 1);
        // fused attention -> ah/al
        flash_kernel<<<BATCH * N_HEADS, 256, flash_smem>>>(Sc);
        // output projection
        mma_gemm_kernel<<<dim3(6, MB), 256, GEMM_SMEM>>>(
            ah, al, Woh, Wol, bo, pP, nullptr, nullptr, D_MODEL, M, D_MODEL, 1);
        // residual + LN1 -> X, ah/al
        ln_kernel<true, true><<<M, 256>>>(pX, pP, ln1g + l * D_MODEL, ln1b + l * D_MODEL,
                                          pX, ah, al);
        // FFN1 (+GELU) -> fh/fl (fp16 h/l)
        mma_gemm_kernel<<<dim3(24, MB), 256, GEMM_SMEM>>>(
            ah, al, W1h, W1l, b1, nullptr, fh, fl, FF_DIM, M, D_MODEL, 1 | 2 | 4);
        // FFN2
        mma_gemm_kernel<<<dim3(6, MB), 256, GEMM_SMEM>>>(
            fh, fl, W2h, W2l, b2, pP, nullptr, nullptr, D_MODEL, M, FF_DIM, 1);
        // residual + LN2 -> X, ah/al
        ln_kernel<true, true><<<M, 256>>>(pX, pP, ln2g + l * D_MODEL, ln2b + l * D_MODEL,
                                          pX, ah, al);
    }

    // --- final LN into d_out --------------------------------------------------
    ln_kernel<false, false><<<M, 256>>>(pX, nullptr, ng, nb, (float*)d_out,
                                        nullptr, nullptr);
    if (tup) {
        pad_out_kernel<<<(BATCH * Sc + 255) / 256, 256>>>(
            (float*)d_out + (size_t)M * D_MODEL, Sc);
    }
}